// round 15
// baseline (speedup 1.0000x reference)
#include <cuda_runtime.h>
#include <cuda_bf16.h>
#include <math.h>
#include <stdint.h>

#define Bb 2
#define Ll 2048
#define Dd 1024
#define LH 8
#define MLEN (Bb * Ll)   // 4096

// ---------------- scratch ----------------
__device__ uint16_t g_xh[MLEN * Dd], g_xl[MLEN * Dd];
__device__ uint16_t g_Wqh[Dd * Dd], g_Wql[Dd * Dd];
__device__ uint16_t g_Wkh[Dd * Dd], g_Wkl[Dd * Dd];
__device__ uint16_t g_Wvh[Dd * Dd], g_Wvl[Dd * Dd];
__device__ uint16_t g_Woh[Dd * Dd], g_Wol[Dd * Dd];
__device__ uint16_t g_Qh[MLEN * Dd], g_Ql[MLEN * Dd];
__device__ uint16_t g_Kh[MLEN * Dd], g_Kl[MLEN * Dd];
__device__ uint16_t g_Vh[MLEN * Dd], g_Vl[MLEN * Dd];
__device__ uint16_t g_Oh[MLEN * Dd], g_Ol[MLEN * Dd];
__device__ float2 g_bstats[32 * 2048 * 32];
__device__ float2 g_rstats[32 * 2048];

// ---------------- helpers ----------------
__device__ __forceinline__ uint32_t smem_u32(const void* p) {
    return (uint32_t)__cvta_generic_to_shared(p);
}

__device__ __forceinline__ void cp_async16(uint32_t dst, const void* src) {
    asm volatile("cp.async.cg.shared.global [%0], [%1], 16;"
                 :: "r"(dst), "l"(src) : "memory");
}
#define CP_COMMIT() asm volatile("cp.async.commit_group;" ::: "memory")
#define CP_WAIT0()  asm volatile("cp.async.wait_group 0;" ::: "memory")
#define CP_WAIT1()  asm volatile("cp.async.wait_group 1;" ::: "memory")

__device__ __forceinline__ void pack_split2(float x0, float x1, uint32_t& h, uint32_t& l) {
    uint32_t u0 = __float_as_uint(x0), u1 = __float_as_uint(x1);
    h = (u0 >> 16) | (u1 & 0xffff0000u);
    float r0 = x0 - __uint_as_float(u0 & 0xffff0000u);
    float r1 = x1 - __uint_as_float(u1 & 0xffff0000u);
    asm("cvt.rn.bf16x2.f32 %0, %1, %2;" : "=r"(l) : "f"(r1), "f"(r0));
}
__device__ __forceinline__ void split_f4(float4 v, uint2& h, uint2& l) {
    pack_split2(v.x, v.y, h.x, l.x);
    pack_split2(v.z, v.w, h.y, l.y);
}

__device__ __forceinline__ void ldsm_x4(uint32_t addr, uint32_t& r0, uint32_t& r1,
                                        uint32_t& r2, uint32_t& r3) {
    asm volatile("ldmatrix.sync.aligned.m8n8.x4.shared.b16 {%0,%1,%2,%3}, [%4];"
                 : "=r"(r0), "=r"(r1), "=r"(r2), "=r"(r3) : "r"(addr));
}
__device__ __forceinline__ void ldsm_x4_t(uint32_t addr, uint32_t& r0, uint32_t& r1,
                                          uint32_t& r2, uint32_t& r3) {
    asm volatile("ldmatrix.sync.aligned.m8n8.x4.trans.shared.b16 {%0,%1,%2,%3}, [%4];"
                 : "=r"(r0), "=r"(r1), "=r"(r2), "=r"(r3) : "r"(addr));
}

__device__ __forceinline__ void mma_bf16(float* c, const uint32_t* a,
                                         uint32_t b0, uint32_t b1) {
    asm volatile(
        "mma.sync.aligned.m16n8k16.row.col.f32.bf16.bf16.f32 "
        "{%0,%1,%2,%3},{%4,%5,%6,%7},{%8,%9},{%0,%1,%2,%3};"
        : "+f"(c[0]), "+f"(c[1]), "+f"(c[2]), "+f"(c[3])
        : "r"(a[0]), "r"(a[1]), "r"(a[2]), "r"(a[3]), "r"(b0), "r"(b1));
}

// ---------------- zero-fill fully-masked local blocks (no data deps) ----------
__global__ void zerofill_kernel(float* __restrict__ attnL) {
    int lin = blockIdx.x;          // 0..1919 = 16 bh * 120 pairs
    int bh = lin / 120;
    int p = lin % 120;
    int r = 0, acc = 0;
    while (acc + (15 - r) <= p) { acc += 15 - r; r++; }
    int cIdx = r + 1 + (p - acc);
    float* dst = attnL + (size_t)bh * Ll * Ll + (size_t)(r * 128) * Ll + cIdx * 128;
    int tid = threadIdx.x;
    float4 z4 = make_float4(0.f, 0.f, 0.f, 0.f);
    #pragma unroll
    for (int i = 0; i < 16; i++) {
        int s = tid + i * 256;
        int row = s >> 5, c4 = s & 31;
        __stcs((float4*)&dst[(size_t)row * Ll + c4 * 4], z4);
    }
}

// ---------------- splits ----------------
__global__ void split_kernel(const float4* __restrict__ src, uint2* __restrict__ h,
                             uint2* __restrict__ l, int n4) {
    int i = blockIdx.x * 256 + threadIdx.x;
    if (i < n4) {
        uint2 hh, ll;
        split_f4(src[i], hh, ll);
        h[i] = hh;
        l[i] = ll;
    }
}

__global__ void split4_kernel(
    const float4* __restrict__ s0, uint2* h0, uint2* l0,
    const float4* __restrict__ s1, uint2* h1, uint2* l1,
    const float4* __restrict__ s2, uint2* h2, uint2* l2,
    const float4* __restrict__ s3, uint2* h3, uint2* l3, int n4)
{
    int z = blockIdx.z;
    const float4* s = (z == 0) ? s0 : (z == 1) ? s1 : (z == 2) ? s2 : s3;
    uint2* h = (z == 0) ? h0 : (z == 1) ? h1 : (z == 2) ? h2 : h3;
    uint2* l = (z == 0) ? l0 : (z == 1) ? l1 : (z == 2) ? l2 : l3;
    int i = blockIdx.x * 256 + threadIdx.x;
    if (i < n4) {
        uint2 hh, ll;
        split_f4(s[i], hh, ll);
        h[i] = hh;
        l[i] = ll;
    }
}

// ---------------- projection GEMM: 128x128, 3-stage cp.async ring -------------
#define PA 24
#define PB2 136
#define GSTAGE 20992
#define GEMM_SMEM (3 * GSTAGE)

__device__ __forceinline__ void gemm_stage3(
    const uint16_t* __restrict__ Ah, const uint16_t* __restrict__ Al,
    const uint16_t* __restrict__ Bh, const uint16_t* __restrict__ Bl,
    uint32_t sb, int buf, int k0, size_t aRow, int colBase,
    int ar, int asel, int brow, int bcol)
{
    const int N = 1024;
    uint32_t st = sb + (uint32_t)buf * GSTAGE;
    uint32_t aO = (uint32_t)(ar * PA + asel) * 2;
    uint32_t bO = (uint32_t)(brow * PB2 + bcol) * 2;
    cp_async16(st + aO, &Ah[aRow + k0 + asel]);
    cp_async16(st + 6144 + aO, &Al[aRow + k0 + asel]);
    cp_async16(st + 12288 + bO, &Bh[(size_t)(k0 + brow) * N + colBase + bcol]);
    cp_async16(st + 16640 + bO, &Bl[(size_t)(k0 + brow) * N + colBase + bcol]);
}

__device__ __forceinline__ void gemm_core(
    const uint16_t* __restrict__ Ah, const uint16_t* __restrict__ Al,
    const uint16_t* __restrict__ Bh, const uint16_t* __restrict__ Bl,
    const float* __restrict__ bias,
    uint16_t* __restrict__ outH, uint16_t* __restrict__ outL,
    float* __restrict__ outF, int mode, uint8_t* dsm, int rowBase)
{
    const int N = 1024, K = 1024;
    int tid = threadIdx.x, lane = tid & 31, wid = tid >> 5;
    int colBase = blockIdx.x * 128;
    int m0 = (wid >> 1) * 32, n0 = (wid & 1) * 64;

    int ar = tid >> 1, asel = (tid & 1) * 8;
    int brow = tid >> 4, bcol = (tid & 15) * 8;

    float c[2][8][4];
    #pragma unroll
    for (int i = 0; i < 2; i++)
        #pragma unroll
        for (int j = 0; j < 8; j++)
            #pragma unroll
            for (int q = 0; q < 4; q++) c[i][j][q] = 0.f;

    uint32_t sb = smem_u32(dsm);
    uint32_t aoff = (((m0 + (lane & 15)) * PA) + (lane >> 4) * 8) * 2;
    uint32_t boff = ((((lane & 7) + ((lane >> 3) & 1) * 8) * PB2) +
                     n0 + (lane >> 4) * 8) * 2;

    size_t aRow = (size_t)(rowBase + ar) * K;
    const int NK = K / 16;

    gemm_stage3(Ah, Al, Bh, Bl, sb, 0, 0, aRow, colBase, ar, asel, brow, bcol);
    CP_COMMIT();
    gemm_stage3(Ah, Al, Bh, Bl, sb, 1, 16, aRow, colBase, ar, asel, brow, bcol);
    CP_COMMIT();

    for (int ks = 0; ks < NK; ks++) {
        CP_WAIT1();
        __syncthreads();
        if (ks + 2 < NK) {
            gemm_stage3(Ah, Al, Bh, Bl, sb, (ks + 2) % 3, (ks + 2) * 16,
                        aRow, colBase, ar, asel, brow, bcol);
            CP_COMMIT();
        }
        uint32_t st = sb + (uint32_t)(ks % 3) * GSTAGE;
        uint32_t afh[2][4], afl[2][4];
        #pragma unroll
        for (int i = 0; i < 2; i++) {
            ldsm_x4(st + aoff + i * 768, afh[i][0], afh[i][1], afh[i][2], afh[i][3]);
            ldsm_x4(st + 6144 + aoff + i * 768, afl[i][0], afl[i][1], afl[i][2], afl[i][3]);
        }
        #pragma unroll
        for (int j = 0; j < 4; j++) {
            uint32_t bh0, bh1, bh2, bh3, bl0, bl1, bl2, bl3;
            ldsm_x4_t(st + 12288 + boff + j * 32, bh0, bh1, bh2, bh3);
            ldsm_x4_t(st + 16640 + boff + j * 32, bl0, bl1, bl2, bl3);
            #pragma unroll
            for (int i = 0; i < 2; i++) {
                mma_bf16(c[i][2 * j], afh[i], bh0, bh1);
                mma_bf16(c[i][2 * j], afh[i], bl0, bl1);
                mma_bf16(c[i][2 * j], afl[i], bh0, bh1);
                mma_bf16(c[i][2 * j + 1], afh[i], bh2, bh3);
                mma_bf16(c[i][2 * j + 1], afh[i], bl2, bl3);
                mma_bf16(c[i][2 * j + 1], afl[i], bh2, bh3);
            }
        }
    }

    int r = lane >> 2, cl2 = (lane & 3) * 2;
    #pragma unroll
    for (int i = 0; i < 2; i++) {
        int row = rowBase + m0 + i * 16 + r;
        #pragma unroll
        for (int j = 0; j < 8; j++) {
            int col = colBase + n0 + j * 8 + cl2;
            float b0 = bias[col], b1 = bias[col + 1];
            if (mode) {
                uint32_t hh, ll;
                pack_split2(c[i][j][0] + b0, c[i][j][1] + b1, hh, ll);
                *(uint32_t*)&outH[(size_t)row * N + col] = hh;
                *(uint32_t*)&outL[(size_t)row * N + col] = ll;
                pack_split2(c[i][j][2] + b0, c[i][j][3] + b1, hh, ll);
                *(uint32_t*)&outH[(size_t)(row + 8) * N + col] = hh;
                *(uint32_t*)&outL[(size_t)(row + 8) * N + col] = ll;
            } else {
                *(float2*)&outF[(size_t)row * N + col] =
                    make_float2(c[i][j][0] + b0, c[i][j][1] + b1);
                *(float2*)&outF[(size_t)(row + 8) * N + col] =
                    make_float2(c[i][j][2] + b0, c[i][j][3] + b1);
            }
        }
    }
}

__global__ __launch_bounds__(256, 2) void gemm_qkv(
    const uint16_t* __restrict__ Ah, const uint16_t* __restrict__ Al,
    const uint16_t* __restrict__ B0h, const uint16_t* __restrict__ B0l,
    const float* __restrict__ bias0, uint16_t* o0h, uint16_t* o0l,
    const uint16_t* __restrict__ B1h, const uint16_t* __restrict__ B1l,
    const float* __restrict__ bias1, uint16_t* o1h, uint16_t* o1l,
    const uint16_t* __restrict__ B2h, const uint16_t* __restrict__ B2l,
    const float* __restrict__ bias2, uint16_t* o2h, uint16_t* o2l)
{
    extern __shared__ __align__(16) uint8_t dsm8[];
    int z = blockIdx.z;
    const uint16_t* Bh = (z == 0) ? B0h : (z == 1) ? B1h : B2h;
    const uint16_t* Bl = (z == 0) ? B0l : (z == 1) ? B1l : B2l;
    const float* bias  = (z == 0) ? bias0 : (z == 1) ? bias1 : bias2;
    uint16_t* outH     = (z == 0) ? o0h : (z == 1) ? o1h : o2h;
    uint16_t* outL     = (z == 0) ? o0l : (z == 1) ? o1l : o2l;
    gemm_core(Ah, Al, Bh, Bl, bias, outH, outL, nullptr, 1, dsm8,
              blockIdx.y * 128);
}

// half-split out-projection: grid (8, 16); rows = b*2048 + (half*8+yy)*128
__global__ __launch_bounds__(256, 2) void gemm_out(
    const uint16_t* __restrict__ Ah, const uint16_t* __restrict__ Al,
    const uint16_t* __restrict__ Bh, const uint16_t* __restrict__ Bl,
    const float* __restrict__ bias, float* __restrict__ outF, int half)
{
    extern __shared__ __align__(16) uint8_t dsm8[];
    int y = blockIdx.y;
    int rowBase = (((y >> 3) * 16) + half * 8 + (y & 7)) * 128;
    gemm_core(Ah, Al, Bh, Bl, bias, nullptr, nullptr, outF, 0, dsm8, rowBase);
}

// ---------------- scores: all K=64 resident, ONE sync -------------------------
#define SC_SMEM 73728
__global__ __launch_bounds__(256, 2) void scores_mma(
    const uint16_t* __restrict__ Qh, const uint16_t* __restrict__ Ql,
    const uint16_t* __restrict__ Kh, const uint16_t* __restrict__ Kl,
    const float* __restrict__ lsc, const float* __restrict__ gsc,
    float* __restrict__ attnL, float* __restrict__ attnG,
    float2* __restrict__ bstats)
{
    int bh = blockIdx.z;
    int b = bh >> 4, h = bh & 15;
    int rowBase = blockIdx.y * 128, colBase = blockIdx.x * 128;
    bool is_local = (h < LH);
    float* dst = is_local ? attnL + (size_t)(b * LH + h) * Ll * Ll
                          : attnG + (size_t)(b * LH + h - LH) * Ll * Ll;
    int tid = threadIdx.x;

    if (is_local && colBase > rowBase) return;   // zero-filled elsewhere
    bool diag = is_local && (colBase == rowBase);
    float scale = 0.125f * (is_local ? lsc[0] : gsc[0]);

    extern __shared__ __align__(16) uint16_t dsm[];
    uint16_t* sQh = dsm;
    uint16_t* sQl = dsm + 9216;
    uint16_t* sKh = dsm + 18432;
    uint16_t* sKl = dsm + 27648;

    int lane = tid & 31, wid = tid >> 5;
    int m0 = (wid >> 1) * 32, n0 = (wid & 1) * 64;

    #pragma unroll
    for (int i = 0; i < 4; i++) {
        int idx = tid + i * 256;
        int row = idx >> 3, cseg = (idx & 7) * 8;
        size_t gq = (size_t)(b * Ll + rowBase + row) * Dd + h * 64 + cseg;
        size_t gk = (size_t)(b * Ll + colBase + row) * Dd + h * 64 + cseg;
        *(uint4*)&sQh[row * 72 + cseg] = *(const uint4*)&Qh[gq];
        *(uint4*)&sQl[row * 72 + cseg] = *(const uint4*)&Ql[gq];
        *(uint4*)&sKh[row * 72 + cseg] = *(const uint4*)&Kh[gk];
        *(uint4*)&sKl[row * 72 + cseg] = *(const uint4*)&Kl[gk];
    }
    __syncthreads();

    float c[2][8][4];
    #pragma unroll
    for (int i = 0; i < 2; i++)
        #pragma unroll
        for (int j = 0; j < 8; j++)
            #pragma unroll
            for (int q = 0; q < 4; q++) c[i][j][q] = 0.f;

    uint32_t sQhA = smem_u32(sQh), sQlA = smem_u32(sQl);
    uint32_t sKhA = smem_u32(sKh), sKlA = smem_u32(sKl);
    uint32_t aoff = (((m0 + (lane & 15)) * 72) + (lane >> 4) * 8) * 2;
    uint32_t boff = (((n0 + (lane & 7) + (lane >> 4) * 8) * 72) +
                     ((lane >> 3) & 1) * 8) * 2;

    #pragma unroll
    for (int kk = 0; kk < 4; kk++) {
        uint32_t afh[2][4], afl[2][4];
        #pragma unroll
        for (int i = 0; i < 2; i++) {
            ldsm_x4(sQhA + aoff + i * 2304 + kk * 32,
                    afh[i][0], afh[i][1], afh[i][2], afh[i][3]);
            ldsm_x4(sQlA + aoff + i * 2304 + kk * 32,
                    afl[i][0], afl[i][1], afl[i][2], afl[i][3]);
        }
        #pragma unroll
        for (int j = 0; j < 4; j++) {
            uint32_t bh0, bh1, bh2, bh3, bl0, bl1, bl2, bl3;
            ldsm_x4(sKhA + boff + j * 2304 + kk * 32, bh0, bh1, bh2, bh3);
            ldsm_x4(sKlA + boff + j * 2304 + kk * 32, bl0, bl1, bl2, bl3);
            #pragma unroll
            for (int i = 0; i < 2; i++) {
                mma_bf16(c[i][2 * j], afh[i], bh0, bh1);
                mma_bf16(c[i][2 * j], afh[i], bl0, bl1);
                mma_bf16(c[i][2 * j], afl[i], bh0, bh1);
                mma_bf16(c[i][2 * j + 1], afh[i], bh2, bh3);
                mma_bf16(c[i][2 * j + 1], afh[i], bl2, bl3);
                mma_bf16(c[i][2 * j + 1], afl[i], bh2, bh3);
            }
        }
    }

    #pragma unroll
    for (int i = 0; i < 2; i++)
        #pragma unroll
        for (int j = 0; j < 8; j++)
            #pragma unroll
            for (int q = 0; q < 4; q++) c[i][j][q] *= scale;

    int r = lane >> 2, cl2 = (lane & 3) * 2;
    int ntile = (colBase + n0) >> 6;

    if (!diag) {
        #pragma unroll
        for (int i = 0; i < 2; i++) {
            #pragma unroll
            for (int half = 0; half < 2; half++) {
                int row = rowBase + m0 + i * 16 + r + half * 8;
                float m = -INFINITY;
                #pragma unroll
                for (int j = 0; j < 8; j++)
                    m = fmaxf(m, fmaxf(c[i][j][half * 2], c[i][j][half * 2 + 1]));
                m = fmaxf(m, __shfl_xor_sync(0xffffffffu, m, 1));
                m = fmaxf(m, __shfl_xor_sync(0xffffffffu, m, 2));
                float s = 0.f;
                #pragma unroll
                for (int j = 0; j < 8; j++) {
                    s += __expf(c[i][j][half * 2] - m);
                    s += __expf(c[i][j][half * 2 + 1] - m);
                }
                s += __shfl_xor_sync(0xffffffffu, s, 1);
                s += __shfl_xor_sync(0xffffffffu, s, 2);
                if ((lane & 3) == 0)
                    bstats[((size_t)bh * 2048 + row) * 32 + ntile] = make_float2(m, s);
                #pragma unroll
                for (int j = 0; j < 8; j++)
                    __stcs((float2*)&dst[(size_t)row * Ll + colBase + n0 + j * 8 + cl2],
                           make_float2(c[i][j][half * 2], c[i][j][half * 2 + 1]));
            }
        }
    } else {
        #pragma unroll
        for (int i = 0; i < 2; i++) {
            #pragma unroll
            for (int half = 0; half < 2; half++) {
                int row = rowBase + m0 + i * 16 + r + half * 8;
                float m = -INFINITY;
                #pragma unroll
                for (int j = 0; j < 8; j++) {
                    int col = colBase + n0 + j * 8 + cl2;
                    float v0 = c[i][j][half * 2], v1 = c[i][j][half * 2 + 1];
                    m = fmaxf(m, (col <= row) ? v0 : -INFINITY);
                    m = fmaxf(m, (col + 1 <= row) ? v1 : -INFINITY);
                }
                m = fmaxf(m, __shfl_xor_sync(0xffffffffu, m, 1));
                m = fmaxf(m, __shfl_xor_sync(0xffffffffu, m, 2));
                float s = 0.f;
                if (m > -1e30f) {
                    #pragma unroll
                    for (int j = 0; j < 8; j++) {
                        int col = colBase + n0 + j * 8 + cl2;
                        s += (col <= row) ? __expf(c[i][j][half * 2] - m) : 0.f;
                        s += (col + 1 <= row) ? __expf(c[i][j][half * 2 + 1] - m) : 0.f;
                    }
                }
                s += __shfl_xor_sync(0xffffffffu, s, 1);
                s += __shfl_xor_sync(0xffffffffu, s, 2);
                if ((lane & 3) == 0)
                    bstats[((size_t)bh * 2048 + row) * 32 + ntile] = make_float2(m, s);
                #pragma unroll
                for (int j = 0; j < 8; j++) {
                    int col = colBase + n0 + j * 8 + cl2;
                    float v0 = (col <= row) ? c[i][j][half * 2] : 0.f;
                    float v1 = (col + 1 <= row) ? c[i][j][half * 2 + 1] : 0.f;
                    __stcs((float2*)&dst[(size_t)row * Ll + col], make_float2(v0, v1));
                }
            }
        }
    }
}

// ---------------- reduce partial stats -> per-row (max, 1/Z) ----------------
__global__ void reduce_stats(const float2* __restrict__ bst, float2* __restrict__ rst) {
    int idx = blockIdx.x * 256 + threadIdx.x;
    int bh = idx >> 11, row = idx & 2047;
    bool is_local = (bh & 15) < LH;
    int jmax = is_local ? (row >> 6) : 31;
    const float2* p = &bst[(size_t)idx * 32];
    float m = -INFINITY;
    for (int j = 0; j <= jmax; j++) m = fmaxf(m, p[j].x);
    float Z = 0.f;
    for (int j = 0; j <= jmax; j++) {
        float2 v = p[j];
        if (v.x > -1e30f) Z += v.y * __expf(v.x - m);
    }
    rst[idx] = make_float2(m, 1.f / Z);
}

// ---------------- AV: chunk=32, pipelined, half-split + LPT -------------------
#define AV_SMEM 75776

__device__ __forceinline__ void av_prefetch(
    uint32_t sb, int buf, int k0,
    const float* __restrict__ P, const uint16_t* __restrict__ Vh,
    const uint16_t* __restrict__ Vl, size_t vB,
    int rowG, int row, int cs, int krow, int cseg)
{
    #pragma unroll
    for (int g = 0; g < 4; g++)
        cp_async16(sb + buf * 18432 + (row * 36 + cs + g * 4) * 4,
                   &P[(size_t)rowG * Ll + k0 + cs + g * 4]);
    uint32_t vdst = sb + 57344 + buf * 9216 + (krow * 72 + cseg) * 2;
    cp_async16(vdst, &Vh[vB + (size_t)(k0 + krow) * Dd + cseg]);
    cp_async16(vdst + 4608, &Vl[vB + (size_t)(k0 + krow) * Dd + cseg]);
}

// half selects rowIdx range [half*8, half*8+8). grid (16,16)=256 CTAs.
__global__ __launch_bounds__(256, 2) void av_mma(
    float* attnL, float* attnG,
    const uint16_t* __restrict__ Vh, const uint16_t* __restrict__ Vl,
    const float2* __restrict__ rst,
    uint16_t* __restrict__ Oh, uint16_t* __restrict__ Ol, int half)
{
    extern __shared__ __align__(16) uint8_t avs[];
    uint32_t sb = smem_u32(avs);

    // LPT within half: global heads first, then local by descending row
    int lin = blockIdx.y * 16 + blockIdx.x;   // 0..255
    int bh, rowIdx;
    if (lin < 128) {
        int gi = lin >> 3;                    // 0..15
        bh = ((gi >> 3) << 4) + 8 + (gi & 7);
        rowIdx = half * 8 + (lin & 7);
    } else {
        int loc = lin - 128;
        rowIdx = half * 8 + 7 - (loc >> 4);
        int sub = loc & 15;
        bh = ((sub >> 3) << 4) + (sub & 7);
    }
    int b = bh >> 4, h = bh & 15;
    int rowBase = rowIdx * 128;
    bool is_local = (h < LH);

    float* P = is_local ? attnL + (size_t)(b * LH + h) * Ll * Ll
                        : attnG + (size_t)(b * LH + h - LH) * Ll * Ll;
    int NK = (is_local ? (rowBase + 128) : Ll) / 32;
    int maskC = is_local ? (rowBase >> 5) : (1 << 30);

    int tid = threadIdx.x, lane = tid & 31, wid = tid >> 5;
    int m0 = (wid >> 1) * 32, n0 = (wid & 1) * 32;

    int row = tid >> 1, cs = (tid & 1) * 16;
    int rowG = rowBase + row;
    float2 st = rst[(size_t)bh * 2048 + rowG];
    int krow = tid >> 3, cseg = (tid & 7) * 8;
    size_t vB = (size_t)(b * Ll) * Dd + h * 64;

    float c[2][4][4];
    #pragma unroll
    for (int i = 0; i < 2; i++)
        #pragma unroll
        for (int j = 0; j < 4; j++)
            #pragma unroll
            for (int q = 0; q < 4; q++) c[i][j][q] = 0.f;

    uint32_t aoff = (((m0 + (lane & 15)) * 40) + (lane >> 4) * 8) * 2;
    uint32_t boff = ((((lane & 7) + ((lane >> 3) & 1) * 8) * 72) +
                     n0 + (lane >> 4) * 8) * 2;

    uint16_t* AhS = (uint16_t*)(avs + 36864);
    uint16_t* AlS = (uint16_t*)(avs + 47104);

    av_prefetch(sb, 0, 0, P, Vh, Vl, vB, rowG, row, cs, krow, cseg);
    CP_COMMIT();

    for (int ck = 0; ck < NK; ck++) {
        int cur = ck & 1;
        int k0 = ck * 32;
        CP_WAIT0();
        __syncthreads();

        {
            const float* rawS = (const float*)(avs + cur * 18432);
            bool needMask = (ck >= maskC);
            float4 p[4];
            #pragma unroll
            for (int g = 0; g < 4; g++) {
                float4 v = *(const float4*)&rawS[row * 36 + cs + g * 4];
                if (!needMask) {
                    p[g].x = __expf(v.x - st.x) * st.y;
                    p[g].y = __expf(v.y - st.x) * st.y;
                    p[g].z = __expf(v.z - st.x) * st.y;
                    p[g].w = __expf(v.w - st.x) * st.y;
                } else {
                    int c0 = k0 + cs + g * 4;
                    p[g].x = (c0 + 0 <= rowG) ? __expf(v.x - st.x) * st.y : 0.f;
                    p[g].y = (c0 + 1 <= rowG) ? __expf(v.y - st.x) * st.y : 0.f;
                    p[g].z = (c0 + 2 <= rowG) ? __expf(v.z - st.x) * st.y : 0.f;
                    p[g].w = (c0 + 3 <= rowG) ? __expf(v.w - st.x) * st.y : 0.f;
                }
                __stcs((float4*)&P[(size_t)rowG * Ll + k0 + cs + g * 4], p[g]);
            }
            uint2 h0, l0, h1, l1, h2, l2, h3, l3;
            split_f4(p[0], h0, l0);
            split_f4(p[1], h1, l1);
            split_f4(p[2], h2, l2);
            split_f4(p[3], h3, l3);
            *(uint4*)&AhS[row * 40 + cs] = make_uint4(h0.x, h0.y, h1.x, h1.y);
            *(uint4*)&AhS[row * 40 + cs + 8] = make_uint4(h2.x, h2.y, h3.x, h3.y);
            *(uint4*)&AlS[row * 40 + cs] = make_uint4(l0.x, l0.y, l1.x, l1.y);
            *(uint4*)&AlS[row * 40 + cs + 8] = make_uint4(l2.x, l2.y, l3.x, l3.y);
        }

        if (ck + 1 < NK) {
            av_prefetch(sb, cur ^ 1, (ck + 1) * 32, P, Vh, Vl, vB,
                        rowG, row, cs, krow, cseg);
            CP_COMMIT();
        }
        __syncthreads();

        uint32_t vhB = sb + 57344 + cur * 9216;
        #pragma unroll
        for (int kk = 0; kk < 2; kk++) {
            uint32_t afh[2][4], afl[2][4];
            #pragma unroll
            for (int i = 0; i < 2; i++) {
                ldsm_x4(sb + 36864 + aoff + kk * 32 + i * 1280,
                        afh[i][0], afh[i][1], afh[i][2], afh[i][3]);
                ldsm_x4(sb + 47104 + aoff + kk * 32 + i * 1280,
                        afl[i][0], afl[i][1], afl[i][2], afl[i][3]);
            }
            #pragma unroll
            for (int j = 0; j < 2; j++) {
                uint32_t bh0, bh1, bh2, bh3, bl0, bl1, bl2, bl3;
                ldsm_x4_t(vhB + boff + kk * 2304 + j * 32, bh0, bh1, bh2, bh3);
                ldsm_x4_t(vhB + 4608 + boff + kk * 2304 + j * 32, bl0, bl1, bl2, bl3);
                #pragma unroll
                for (int i = 0; i < 2; i++) {
                    mma_bf16(c[i][2 * j], afh[i], bh0, bh1);
                    mma_bf16(c[i][2 * j], afh[i], bl0, bl1);
                    mma_bf16(c[i][2 * j], afl[i], bh0, bh1);
                    mma_bf16(c[i][2 * j + 1], afh[i], bh2, bh3);
                    mma_bf16(c[i][2 * j + 1], afh[i], bl2, bl3);
                    mma_bf16(c[i][2 * j + 1], afl[i], bh2, bh3);
                }
            }
        }
    }

    int r = lane >> 2, cl2 = (lane & 3) * 2;
    #pragma unroll
    for (int i = 0; i < 2; i++) {
        int orow = rowBase + m0 + i * 16 + r;
        #pragma unroll
        for (int j = 0; j < 4; j++) {
            int col = n0 + j * 8 + cl2;
            size_t off0 = (size_t)(b * Ll + orow) * Dd + h * 64 + col;
            size_t off1 = (size_t)(b * Ll + orow + 8) * Dd + h * 64 + col;
            uint32_t hh, ll;
            pack_split2(c[i][j][0], c[i][j][1], hh, ll);
            *(uint32_t*)&Oh[off0] = hh;
            *(uint32_t*)&Ol[off0] = ll;
            pack_split2(c[i][j][2], c[i][j][3], hh, ll);
            *(uint32_t*)&Oh[off1] = hh;
            *(uint32_t*)&Ol[off1] = ll;
        }
    }
}

// ---------------- launch ----------------
extern "C" void kernel_launch(void* const* d_in, const int* in_sizes, int n_in,
                              void* d_out, int out_size)
{
    const float* x   = (const float*)d_in[0];
    const float* Wq  = (const float*)d_in[1];
    const float* bq  = (const float*)d_in[2];
    const float* Wk  = (const float*)d_in[3];
    const float* bk  = (const float*)d_in[4];
    const float* Wv  = (const float*)d_in[5];
    const float* bv  = (const float*)d_in[6];
    const float* Wo  = (const float*)d_in[7];
    const float* bo  = (const float*)d_in[8];
    const float* lsc = (const float*)d_in[9];
    const float* gsc = (const float*)d_in[10];

    float* out   = (float*)d_out;
    float* attnL = out + (size_t)MLEN * Dd;
    float* attnG = attnL + (size_t)Bb * LH * Ll * Ll;

    uint16_t *xh, *xl, *Wqh, *Wql, *Wkh, *Wkl, *Wvh, *Wvl, *Woh, *Wol;
    uint16_t *Qh, *Ql, *Kh, *Kl, *Vh, *Vl, *Ohp, *Olp;
    float2 *bst, *rstp;
    cudaGetSymbolAddress((void**)&xh, g_xh);   cudaGetSymbolAddress((void**)&xl, g_xl);
    cudaGetSymbolAddress((void**)&Wqh, g_Wqh); cudaGetSymbolAddress((void**)&Wql, g_Wql);
    cudaGetSymbolAddress((void**)&Wkh, g_Wkh); cudaGetSymbolAddress((void**)&Wkl, g_Wkl);
    cudaGetSymbolAddress((void**)&Wvh, g_Wvh); cudaGetSymbolAddress((void**)&Wvl, g_Wvl);
    cudaGetSymbolAddress((void**)&Woh, g_Woh); cudaGetSymbolAddress((void**)&Wol, g_Wol);
    cudaGetSymbolAddress((void**)&Qh, g_Qh);   cudaGetSymbolAddress((void**)&Ql, g_Ql);
    cudaGetSymbolAddress((void**)&Kh, g_Kh);   cudaGetSymbolAddress((void**)&Kl, g_Kl);
    cudaGetSymbolAddress((void**)&Vh, g_Vh);   cudaGetSymbolAddress((void**)&Vl, g_Vl);
    cudaGetSymbolAddress((void**)&Ohp, g_Oh);  cudaGetSymbolAddress((void**)&Olp, g_Ol);
    cudaGetSymbolAddress((void**)&bst, g_bstats);
    cudaGetSymbolAddress((void**)&rstp, g_rstats);

    cudaFuncSetAttribute(scores_mma, cudaFuncAttributeMaxDynamicSharedMemorySize, SC_SMEM);
    cudaFuncSetAttribute(av_mma, cudaFuncAttributeMaxDynamicSharedMemorySize, AV_SMEM);
    cudaFuncSetAttribute(gemm_qkv, cudaFuncAttributeMaxDynamicSharedMemorySize, GEMM_SMEM);
    cudaFuncSetAttribute(gemm_out, cudaFuncAttributeMaxDynamicSharedMemorySize, GEMM_SMEM);

    static cudaStream_t s2 = nullptr;
    static cudaEvent_t evFork = nullptr, evSplit = nullptr, evV = nullptr;
    static cudaEvent_t evAvA = nullptr, evOutA = nullptr;
    if (!s2) {
        cudaStreamCreateWithFlags(&s2, cudaStreamNonBlocking);
        cudaEventCreateWithFlags(&evFork, cudaEventDisableTiming);
        cudaEventCreateWithFlags(&evSplit, cudaEventDisableTiming);
        cudaEventCreateWithFlags(&evV, cudaEventDisableTiming);
        cudaEventCreateWithFlags(&evAvA, cudaEventDisableTiming);
        cudaEventCreateWithFlags(&evOutA, cudaEventDisableTiming);
    }

    int nx4 = MLEN * Dd / 4;
    int nw4 = Dd * Dd / 4;

    // fork s2; zerofill has no data deps
    cudaEventRecord(evFork, 0);
    cudaStreamWaitEvent(s2, evFork, 0);
    zerofill_kernel<<<1920, 256, 0, s2>>>(attnL);

    split_kernel<<<nx4 / 256, 256>>>((const float4*)x, (uint2*)xh, (uint2*)xl, nx4);
    split4_kernel<<<dim3(nw4 / 256, 1, 4), 256>>>(
        (const float4*)Wq, (uint2*)Wqh, (uint2*)Wql,
        (const float4*)Wk, (uint2*)Wkh, (uint2*)Wkl,
        (const float4*)Wv, (uint2*)Wvh, (uint2*)Wvl,
        (const float4*)Wo, (uint2*)Woh, (uint2*)Wol, nw4);
    cudaEventRecord(evSplit, 0);
    cudaStreamWaitEvent(s2, evSplit, 0);

    // V-projection on s2 (only needed by av_mma)
    gemm_qkv<<<dim3(8, 32, 1), 256, GEMM_SMEM, s2>>>(xh, xl,
        Wvh, Wvl, bv, Vh, Vl,
        Wvh, Wvl, bv, Vh, Vl,
        Wvh, Wvl, bv, Vh, Vl);
    cudaEventRecord(evV, s2);

    // Q,K projections on main
    gemm_qkv<<<dim3(8, 32, 2), 256, GEMM_SMEM>>>(xh, xl,
        Wqh, Wql, bq, Qh, Ql,
        Wkh, Wkl, bk, Kh, Kl,
        Wkh, Wkl, bk, Kh, Kl);

    scores_mma<<<dim3(16, 16, 32), 256, SC_SMEM>>>(Qh, Ql, Kh, Kl, lsc, gsc,
                                                   attnL, attnG, bst);
    reduce_stats<<<256, 256>>>(bst, rstp);

    cudaStreamWaitEvent(0, evV, 0);   // join V (and zerofill) before AV

    // AV half A (token rows [0,1024) per batch), then event for out-proj A
    av_mma<<<dim3(16, 16), 256, AV_SMEM>>>(attnL, attnG, Vh, Vl, rstp, Ohp, Olp, 0);
    cudaEventRecord(evAvA, 0);

    // out-proj A on s2, overlapping AV half B on main
    cudaStreamWaitEvent(s2, evAvA, 0);
    gemm_out<<<dim3(8, 16), 256, GEMM_SMEM, s2>>>(Ohp, Olp, Woh, Wol, bo, out, 0);
    cudaEventRecord(evOutA, s2);

    av_mma<<<dim3(16, 16), 256, AV_SMEM>>>(attnL, attnG, Vh, Vl, rstp, Ohp, Olp, 1);
    gemm_out<<<dim3(8, 16), 256, GEMM_SMEM>>>(Ohp, Olp, Woh, Wol, bo, out, 1);

    cudaStreamWaitEvent(0, evOutA, 0);   // join s2 back before capture ends
}

// round 16
// speedup vs baseline: 1.0616x; 1.0616x over previous
#include <cuda_runtime.h>
#include <cuda_bf16.h>
#include <math.h>
#include <stdint.h>

#define Bb 2
#define Ll 2048
#define Dd 1024
#define LH 8
#define MLEN (Bb * Ll)   // 4096

// ---------------- scratch ----------------
__device__ uint16_t g_xh[MLEN * Dd], g_xl[MLEN * Dd];
__device__ uint16_t g_Wqh[Dd * Dd], g_Wql[Dd * Dd];
__device__ uint16_t g_Wkh[Dd * Dd], g_Wkl[Dd * Dd];
__device__ uint16_t g_Wvh[Dd * Dd], g_Wvl[Dd * Dd];
__device__ uint16_t g_Woh[Dd * Dd], g_Wol[Dd * Dd];
__device__ uint16_t g_Qh[MLEN * Dd], g_Ql[MLEN * Dd];
__device__ uint16_t g_Kh[MLEN * Dd], g_Kl[MLEN * Dd];
__device__ uint16_t g_Vh[MLEN * Dd], g_Vl[MLEN * Dd];
__device__ uint16_t g_Oh[MLEN * Dd], g_Ol[MLEN * Dd];
__device__ float2 g_bstats[32 * 2048 * 32];

// ---------------- helpers ----------------
__device__ __forceinline__ uint32_t smem_u32(const void* p) {
    return (uint32_t)__cvta_generic_to_shared(p);
}

__device__ __forceinline__ void cp_async16(uint32_t dst, const void* src) {
    asm volatile("cp.async.cg.shared.global [%0], [%1], 16;"
                 :: "r"(dst), "l"(src) : "memory");
}
#define CP_COMMIT() asm volatile("cp.async.commit_group;" ::: "memory")
#define CP_WAIT0()  asm volatile("cp.async.wait_group 0;" ::: "memory")
#define CP_WAIT1()  asm volatile("cp.async.wait_group 1;" ::: "memory")

__device__ __forceinline__ void pack_split2(float x0, float x1, uint32_t& h, uint32_t& l) {
    uint32_t u0 = __float_as_uint(x0), u1 = __float_as_uint(x1);
    h = (u0 >> 16) | (u1 & 0xffff0000u);
    float r0 = x0 - __uint_as_float(u0 & 0xffff0000u);
    float r1 = x1 - __uint_as_float(u1 & 0xffff0000u);
    asm("cvt.rn.bf16x2.f32 %0, %1, %2;" : "=r"(l) : "f"(r1), "f"(r0));
}
__device__ __forceinline__ void split_f4(float4 v, uint2& h, uint2& l) {
    pack_split2(v.x, v.y, h.x, l.x);
    pack_split2(v.z, v.w, h.y, l.y);
}

__device__ __forceinline__ void ldsm_x4(uint32_t addr, uint32_t& r0, uint32_t& r1,
                                        uint32_t& r2, uint32_t& r3) {
    asm volatile("ldmatrix.sync.aligned.m8n8.x4.shared.b16 {%0,%1,%2,%3}, [%4];"
                 : "=r"(r0), "=r"(r1), "=r"(r2), "=r"(r3) : "r"(addr));
}
__device__ __forceinline__ void ldsm_x4_t(uint32_t addr, uint32_t& r0, uint32_t& r1,
                                          uint32_t& r2, uint32_t& r3) {
    asm volatile("ldmatrix.sync.aligned.m8n8.x4.trans.shared.b16 {%0,%1,%2,%3}, [%4];"
                 : "=r"(r0), "=r"(r1), "=r"(r2), "=r"(r3) : "r"(addr));
}

__device__ __forceinline__ void mma_bf16(float* c, const uint32_t* a,
                                         uint32_t b0, uint32_t b1) {
    asm volatile(
        "mma.sync.aligned.m16n8k16.row.col.f32.bf16.bf16.f32 "
        "{%0,%1,%2,%3},{%4,%5,%6,%7},{%8,%9},{%0,%1,%2,%3};"
        : "+f"(c[0]), "+f"(c[1]), "+f"(c[2]), "+f"(c[3])
        : "r"(a[0]), "r"(a[1]), "r"(a[2]), "r"(a[3]), "r"(b0), "r"(b1));
}

// ---------------- zero-fill fully-masked local blocks (no data deps) ----------
__global__ void zerofill_kernel(float* __restrict__ attnL) {
    int lin = blockIdx.x;          // 0..1919 = 16 bh * 120 pairs
    int bh = lin / 120;
    int p = lin % 120;
    int r = 0, acc = 0;
    while (acc + (15 - r) <= p) { acc += 15 - r; r++; }
    int cIdx = r + 1 + (p - acc);
    float* dst = attnL + (size_t)bh * Ll * Ll + (size_t)(r * 128) * Ll + cIdx * 128;
    int tid = threadIdx.x;
    float4 z4 = make_float4(0.f, 0.f, 0.f, 0.f);
    #pragma unroll
    for (int i = 0; i < 16; i++) {
        int s = tid + i * 256;
        int row = s >> 5, c4 = s & 31;
        __stcs((float4*)&dst[(size_t)row * Ll + c4 * 4], z4);
    }
}

// ---------------- splits ----------------
__global__ void split_kernel(const float4* __restrict__ src, uint2* __restrict__ h,
                             uint2* __restrict__ l, int n4) {
    int i = blockIdx.x * 256 + threadIdx.x;
    if (i < n4) {
        uint2 hh, ll;
        split_f4(src[i], hh, ll);
        h[i] = hh;
        l[i] = ll;
    }
}

__global__ void split4_kernel(
    const float4* __restrict__ s0, uint2* h0, uint2* l0,
    const float4* __restrict__ s1, uint2* h1, uint2* l1,
    const float4* __restrict__ s2, uint2* h2, uint2* l2,
    const float4* __restrict__ s3, uint2* h3, uint2* l3, int n4)
{
    int z = blockIdx.z;
    const float4* s = (z == 0) ? s0 : (z == 1) ? s1 : (z == 2) ? s2 : s3;
    uint2* h = (z == 0) ? h0 : (z == 1) ? h1 : (z == 2) ? h2 : h3;
    uint2* l = (z == 0) ? l0 : (z == 1) ? l1 : (z == 2) ? l2 : l3;
    int i = blockIdx.x * 256 + threadIdx.x;
    if (i < n4) {
        uint2 hh, ll;
        split_f4(s[i], hh, ll);
        h[i] = hh;
        l[i] = ll;
    }
}

// ---------------- projection GEMM: 128x128, 3-stage cp.async ring -------------
#define PA 24
#define PB2 136
#define GSTAGE 20992
#define GEMM_SMEM (3 * GSTAGE)

__device__ __forceinline__ void gemm_stage3(
    const uint16_t* __restrict__ Ah, const uint16_t* __restrict__ Al,
    const uint16_t* __restrict__ Bh, const uint16_t* __restrict__ Bl,
    uint32_t sb, int buf, int k0, size_t aRow, int colBase,
    int ar, int asel, int brow, int bcol)
{
    const int N = 1024;
    uint32_t st = sb + (uint32_t)buf * GSTAGE;
    uint32_t aO = (uint32_t)(ar * PA + asel) * 2;
    uint32_t bO = (uint32_t)(brow * PB2 + bcol) * 2;
    cp_async16(st + aO, &Ah[aRow + k0 + asel]);
    cp_async16(st + 6144 + aO, &Al[aRow + k0 + asel]);
    cp_async16(st + 12288 + bO, &Bh[(size_t)(k0 + brow) * N + colBase + bcol]);
    cp_async16(st + 16640 + bO, &Bl[(size_t)(k0 + brow) * N + colBase + bcol]);
}

__device__ __forceinline__ void gemm_core(
    const uint16_t* __restrict__ Ah, const uint16_t* __restrict__ Al,
    const uint16_t* __restrict__ Bh, const uint16_t* __restrict__ Bl,
    const float* __restrict__ bias,
    uint16_t* __restrict__ outH, uint16_t* __restrict__ outL,
    float* __restrict__ outF, int mode, uint8_t* dsm)
{
    const int N = 1024, K = 1024;
    int tid = threadIdx.x, lane = tid & 31, wid = tid >> 5;
    int rowBase = blockIdx.y * 128, colBase = blockIdx.x * 128;
    int m0 = (wid >> 1) * 32, n0 = (wid & 1) * 64;

    int ar = tid >> 1, asel = (tid & 1) * 8;
    int brow = tid >> 4, bcol = (tid & 15) * 8;

    float c[2][8][4];
    #pragma unroll
    for (int i = 0; i < 2; i++)
        #pragma unroll
        for (int j = 0; j < 8; j++)
            #pragma unroll
            for (int q = 0; q < 4; q++) c[i][j][q] = 0.f;

    uint32_t sb = smem_u32(dsm);
    uint32_t aoff = (((m0 + (lane & 15)) * PA) + (lane >> 4) * 8) * 2;
    uint32_t boff = ((((lane & 7) + ((lane >> 3) & 1) * 8) * PB2) +
                     n0 + (lane >> 4) * 8) * 2;

    size_t aRow = (size_t)(rowBase + ar) * K;
    const int NK = K / 16;

    gemm_stage3(Ah, Al, Bh, Bl, sb, 0, 0, aRow, colBase, ar, asel, brow, bcol);
    CP_COMMIT();
    gemm_stage3(Ah, Al, Bh, Bl, sb, 1, 16, aRow, colBase, ar, asel, brow, bcol);
    CP_COMMIT();

    for (int ks = 0; ks < NK; ks++) {
        CP_WAIT1();
        __syncthreads();
        if (ks + 2 < NK) {
            gemm_stage3(Ah, Al, Bh, Bl, sb, (ks + 2) % 3, (ks + 2) * 16,
                        aRow, colBase, ar, asel, brow, bcol);
            CP_COMMIT();
        }
        uint32_t st = sb + (uint32_t)(ks % 3) * GSTAGE;
        uint32_t afh[2][4], afl[2][4];
        #pragma unroll
        for (int i = 0; i < 2; i++) {
            ldsm_x4(st + aoff + i * 768, afh[i][0], afh[i][1], afh[i][2], afh[i][3]);
            ldsm_x4(st + 6144 + aoff + i * 768, afl[i][0], afl[i][1], afl[i][2], afl[i][3]);
        }
        #pragma unroll
        for (int j = 0; j < 4; j++) {
            uint32_t bh0, bh1, bh2, bh3, bl0, bl1, bl2, bl3;
            ldsm_x4_t(st + 12288 + boff + j * 32, bh0, bh1, bh2, bh3);
            ldsm_x4_t(st + 16640 + boff + j * 32, bl0, bl1, bl2, bl3);
            #pragma unroll
            for (int i = 0; i < 2; i++) {
                mma_bf16(c[i][2 * j], afh[i], bh0, bh1);
                mma_bf16(c[i][2 * j], afh[i], bl0, bl1);
                mma_bf16(c[i][2 * j], afl[i], bh0, bh1);
                mma_bf16(c[i][2 * j + 1], afh[i], bh2, bh3);
                mma_bf16(c[i][2 * j + 1], afh[i], bl2, bl3);
                mma_bf16(c[i][2 * j + 1], afl[i], bh2, bh3);
            }
        }
    }

    int r = lane >> 2, cl2 = (lane & 3) * 2;
    #pragma unroll
    for (int i = 0; i < 2; i++) {
        int row = rowBase + m0 + i * 16 + r;
        #pragma unroll
        for (int j = 0; j < 8; j++) {
            int col = colBase + n0 + j * 8 + cl2;
            float b0 = bias[col], b1 = bias[col + 1];
            if (mode) {
                uint32_t hh, ll;
                pack_split2(c[i][j][0] + b0, c[i][j][1] + b1, hh, ll);
                *(uint32_t*)&outH[(size_t)row * N + col] = hh;
                *(uint32_t*)&outL[(size_t)row * N + col] = ll;
                pack_split2(c[i][j][2] + b0, c[i][j][3] + b1, hh, ll);
                *(uint32_t*)&outH[(size_t)(row + 8) * N + col] = hh;
                *(uint32_t*)&outL[(size_t)(row + 8) * N + col] = ll;
            } else {
                *(float2*)&outF[(size_t)row * N + col] =
                    make_float2(c[i][j][0] + b0, c[i][j][1] + b1);
                *(float2*)&outF[(size_t)(row + 8) * N + col] =
                    make_float2(c[i][j][2] + b0, c[i][j][3] + b1);
            }
        }
    }
}

__global__ __launch_bounds__(256, 2) void gemm_qkv(
    const uint16_t* __restrict__ Ah, const uint16_t* __restrict__ Al,
    const uint16_t* __restrict__ B0h, const uint16_t* __restrict__ B0l,
    const float* __restrict__ bias0, uint16_t* o0h, uint16_t* o0l,
    const uint16_t* __restrict__ B1h, const uint16_t* __restrict__ B1l,
    const float* __restrict__ bias1, uint16_t* o1h, uint16_t* o1l,
    const uint16_t* __restrict__ B2h, const uint16_t* __restrict__ B2l,
    const float* __restrict__ bias2, uint16_t* o2h, uint16_t* o2l)
{
    extern __shared__ __align__(16) uint8_t dsm8[];
    int z = blockIdx.z;
    const uint16_t* Bh = (z == 0) ? B0h : (z == 1) ? B1h : B2h;
    const uint16_t* Bl = (z == 0) ? B0l : (z == 1) ? B1l : B2l;
    const float* bias  = (z == 0) ? bias0 : (z == 1) ? bias1 : bias2;
    uint16_t* outH     = (z == 0) ? o0h : (z == 1) ? o1h : o2h;
    uint16_t* outL     = (z == 0) ? o0l : (z == 1) ? o1l : o2l;
    gemm_core(Ah, Al, Bh, Bl, bias, outH, outL, nullptr, 1, dsm8);
}

__global__ __launch_bounds__(256, 2) void gemm_out(
    const uint16_t* __restrict__ Ah, const uint16_t* __restrict__ Al,
    const uint16_t* __restrict__ Bh, const uint16_t* __restrict__ Bl,
    const float* __restrict__ bias, float* __restrict__ outF)
{
    extern __shared__ __align__(16) uint8_t dsm8[];
    gemm_core(Ah, Al, Bh, Bl, bias, nullptr, nullptr, outF, 0, dsm8);
}

// ---------------- scores: all K=64 resident, ONE sync -------------------------
#define SC_SMEM 73728
__global__ __launch_bounds__(256, 2) void scores_mma(
    const uint16_t* __restrict__ Qh, const uint16_t* __restrict__ Ql,
    const uint16_t* __restrict__ Kh, const uint16_t* __restrict__ Kl,
    const float* __restrict__ lsc, const float* __restrict__ gsc,
    float* __restrict__ attnL, float* __restrict__ attnG,
    float2* __restrict__ bstats)
{
    int bh = blockIdx.z;
    int b = bh >> 4, h = bh & 15;
    int rowBase = blockIdx.y * 128, colBase = blockIdx.x * 128;
    bool is_local = (h < LH);
    float* dst = is_local ? attnL + (size_t)(b * LH + h) * Ll * Ll
                          : attnG + (size_t)(b * LH + h - LH) * Ll * Ll;
    int tid = threadIdx.x;

    if (is_local && colBase > rowBase) return;   // zero-filled elsewhere
    bool diag = is_local && (colBase == rowBase);
    float scale = 0.125f * (is_local ? lsc[0] : gsc[0]);

    extern __shared__ __align__(16) uint16_t dsm[];
    uint16_t* sQh = dsm;
    uint16_t* sQl = dsm + 9216;
    uint16_t* sKh = dsm + 18432;
    uint16_t* sKl = dsm + 27648;

    int lane = tid & 31, wid = tid >> 5;
    int m0 = (wid >> 1) * 32, n0 = (wid & 1) * 64;

    #pragma unroll
    for (int i = 0; i < 4; i++) {
        int idx = tid + i * 256;
        int row = idx >> 3, cseg = (idx & 7) * 8;
        size_t gq = (size_t)(b * Ll + rowBase + row) * Dd + h * 64 + cseg;
        size_t gk = (size_t)(b * Ll + colBase + row) * Dd + h * 64 + cseg;
        *(uint4*)&sQh[row * 72 + cseg] = *(const uint4*)&Qh[gq];
        *(uint4*)&sQl[row * 72 + cseg] = *(const uint4*)&Ql[gq];
        *(uint4*)&sKh[row * 72 + cseg] = *(const uint4*)&Kh[gk];
        *(uint4*)&sKl[row * 72 + cseg] = *(const uint4*)&Kl[gk];
    }
    __syncthreads();

    float c[2][8][4];
    #pragma unroll
    for (int i = 0; i < 2; i++)
        #pragma unroll
        for (int j = 0; j < 8; j++)
            #pragma unroll
            for (int q = 0; q < 4; q++) c[i][j][q] = 0.f;

    uint32_t sQhA = smem_u32(sQh), sQlA = smem_u32(sQl);
    uint32_t sKhA = smem_u32(sKh), sKlA = smem_u32(sKl);
    uint32_t aoff = (((m0 + (lane & 15)) * 72) + (lane >> 4) * 8) * 2;
    uint32_t boff = (((n0 + (lane & 7) + (lane >> 4) * 8) * 72) +
                     ((lane >> 3) & 1) * 8) * 2;

    #pragma unroll
    for (int kk = 0; kk < 4; kk++) {
        uint32_t afh[2][4], afl[2][4];
        #pragma unroll
        for (int i = 0; i < 2; i++) {
            ldsm_x4(sQhA + aoff + i * 2304 + kk * 32,
                    afh[i][0], afh[i][1], afh[i][2], afh[i][3]);
            ldsm_x4(sQlA + aoff + i * 2304 + kk * 32,
                    afl[i][0], afl[i][1], afl[i][2], afl[i][3]);
        }
        #pragma unroll
        for (int j = 0; j < 4; j++) {
            uint32_t bh0, bh1, bh2, bh3, bl0, bl1, bl2, bl3;
            ldsm_x4(sKhA + boff + j * 2304 + kk * 32, bh0, bh1, bh2, bh3);
            ldsm_x4(sKlA + boff + j * 2304 + kk * 32, bl0, bl1, bl2, bl3);
            #pragma unroll
            for (int i = 0; i < 2; i++) {
                mma_bf16(c[i][2 * j], afh[i], bh0, bh1);
                mma_bf16(c[i][2 * j], afh[i], bl0, bl1);
                mma_bf16(c[i][2 * j], afl[i], bh0, bh1);
                mma_bf16(c[i][2 * j + 1], afh[i], bh2, bh3);
                mma_bf16(c[i][2 * j + 1], afh[i], bl2, bl3);
                mma_bf16(c[i][2 * j + 1], afl[i], bh2, bh3);
            }
        }
    }

    #pragma unroll
    for (int i = 0; i < 2; i++)
        #pragma unroll
        for (int j = 0; j < 8; j++)
            #pragma unroll
            for (int q = 0; q < 4; q++) c[i][j][q] *= scale;

    int r = lane >> 2, cl2 = (lane & 3) * 2;
    int ntile = (colBase + n0) >> 6;

    if (!diag) {
        #pragma unroll
        for (int i = 0; i < 2; i++) {
            #pragma unroll
            for (int half = 0; half < 2; half++) {
                int row = rowBase + m0 + i * 16 + r + half * 8;
                float m = -INFINITY;
                #pragma unroll
                for (int j = 0; j < 8; j++)
                    m = fmaxf(m, fmaxf(c[i][j][half * 2], c[i][j][half * 2 + 1]));
                m = fmaxf(m, __shfl_xor_sync(0xffffffffu, m, 1));
                m = fmaxf(m, __shfl_xor_sync(0xffffffffu, m, 2));
                float s = 0.f;
                #pragma unroll
                for (int j = 0; j < 8; j++) {
                    s += __expf(c[i][j][half * 2] - m);
                    s += __expf(c[i][j][half * 2 + 1] - m);
                }
                s += __shfl_xor_sync(0xffffffffu, s, 1);
                s += __shfl_xor_sync(0xffffffffu, s, 2);
                if ((lane & 3) == 0)
                    bstats[((size_t)bh * 2048 + row) * 32 + ntile] = make_float2(m, s);
                #pragma unroll
                for (int j = 0; j < 8; j++)
                    __stcs((float2*)&dst[(size_t)row * Ll + colBase + n0 + j * 8 + cl2],
                           make_float2(c[i][j][half * 2], c[i][j][half * 2 + 1]));
            }
        }
    } else {
        #pragma unroll
        for (int i = 0; i < 2; i++) {
            #pragma unroll
            for (int half = 0; half < 2; half++) {
                int row = rowBase + m0 + i * 16 + r + half * 8;
                float m = -INFINITY;
                #pragma unroll
                for (int j = 0; j < 8; j++) {
                    int col = colBase + n0 + j * 8 + cl2;
                    float v0 = c[i][j][half * 2], v1 = c[i][j][half * 2 + 1];
                    m = fmaxf(m, (col <= row) ? v0 : -INFINITY);
                    m = fmaxf(m, (col + 1 <= row) ? v1 : -INFINITY);
                }
                m = fmaxf(m, __shfl_xor_sync(0xffffffffu, m, 1));
                m = fmaxf(m, __shfl_xor_sync(0xffffffffu, m, 2));
                float s = 0.f;
                if (m > -1e30f) {
                    #pragma unroll
                    for (int j = 0; j < 8; j++) {
                        int col = colBase + n0 + j * 8 + cl2;
                        s += (col <= row) ? __expf(c[i][j][half * 2] - m) : 0.f;
                        s += (col + 1 <= row) ? __expf(c[i][j][half * 2 + 1] - m) : 0.f;
                    }
                }
                s += __shfl_xor_sync(0xffffffffu, s, 1);
                s += __shfl_xor_sync(0xffffffffu, s, 2);
                if ((lane & 3) == 0)
                    bstats[((size_t)bh * 2048 + row) * 32 + ntile] = make_float2(m, s);
                #pragma unroll
                for (int j = 0; j < 8; j++) {
                    int col = colBase + n0 + j * 8 + cl2;
                    float v0 = (col <= row) ? c[i][j][half * 2] : 0.f;
                    float v1 = (col + 1 <= row) ? c[i][j][half * 2 + 1] : 0.f;
                    __stcs((float2*)&dst[(size_t)row * Ll + col], make_float2(v0, v1));
                }
            }
        }
    }
}

// ---------------- AV: chunk=32, pipelined, LPT order, inline stats reduce -----
#define AV_SMEM 75776

__device__ __forceinline__ void av_prefetch(
    uint32_t sb, int buf, int k0,
    const float* __restrict__ P, const uint16_t* __restrict__ Vh,
    const uint16_t* __restrict__ Vl, size_t vB,
    int rowG, int row, int cs, int krow, int cseg)
{
    #pragma unroll
    for (int g = 0; g < 4; g++)
        cp_async16(sb + buf * 18432 + (row * 36 + cs + g * 4) * 4,
                   &P[(size_t)rowG * Ll + k0 + cs + g * 4]);
    uint32_t vdst = sb + 57344 + buf * 9216 + (krow * 72 + cseg) * 2;
    cp_async16(vdst, &Vh[vB + (size_t)(k0 + krow) * Dd + cseg]);
    cp_async16(vdst + 4608, &Vl[vB + (size_t)(k0 + krow) * Dd + cseg]);
}

__global__ __launch_bounds__(256, 2) void av_mma(
    float* attnL, float* attnG,
    const uint16_t* __restrict__ Vh, const uint16_t* __restrict__ Vl,
    const float2* __restrict__ bst,
    uint16_t* __restrict__ Oh, uint16_t* __restrict__ Ol)
{
    extern __shared__ __align__(16) uint8_t avs[];
    uint32_t sb = smem_u32(avs);

    // LPT remap: heavy CTAs (global heads) first, then local by descending row
    int lin = blockIdx.y * 16 + blockIdx.x;
    int bh, rowIdx;
    if (lin < 256) {
        bh = ((lin >> 7) << 4) + 8 + ((lin >> 4) & 7);
        rowIdx = lin & 15;
    } else {
        int loc = lin - 256;
        rowIdx = 15 - (loc >> 4);
        int sub = loc & 15;
        bh = ((sub >> 3) << 4) + (sub & 7);
    }
    int b = bh >> 4, h = bh & 15;
    int rowBase = rowIdx * 128;
    bool is_local = (h < LH);

    float* P = is_local ? attnL + (size_t)(b * LH + h) * Ll * Ll
                        : attnG + (size_t)(b * LH + h - LH) * Ll * Ll;
    int NK = (is_local ? (rowBase + 128) : Ll) / 32;
    int maskC = is_local ? (rowBase >> 5) : (1 << 30);

    int tid = threadIdx.x, lane = tid & 31, wid = tid >> 5;
    int m0 = (wid >> 1) * 32, n0 = (wid & 1) * 32;

    int row = tid >> 1, cs = (tid & 1) * 16;
    int rowG = rowBase + row;
    int krow = tid >> 3, cseg = (tid & 7) * 8;
    size_t vB = (size_t)(b * Ll) * Dd + h * 64;

    float c[2][4][4];
    #pragma unroll
    for (int i = 0; i < 2; i++)
        #pragma unroll
        for (int j = 0; j < 4; j++)
            #pragma unroll
            for (int q = 0; q < 4; q++) c[i][j][q] = 0.f;

    uint32_t aoff = (((m0 + (lane & 15)) * 40) + (lane >> 4) * 8) * 2;
    uint32_t boff = ((((lane & 7) + ((lane >> 3) & 1) * 8) * 72) +
                     n0 + (lane >> 4) * 8) * 2;

    uint16_t* AhS = (uint16_t*)(avs + 36864);
    uint16_t* AlS = (uint16_t*)(avs + 47104);

    // first prefetch in flight, then compute per-row softmax stats inline
    av_prefetch(sb, 0, 0, P, Vh, Vl, vB, rowG, row, cs, krow, cseg);
    CP_COMMIT();

    float2 st;
    {
        const float2* p = &bst[((size_t)bh * 2048 + rowG) * 32];
        int jmax = is_local ? (rowG >> 6) : 31;
        float m = -INFINITY;
        for (int j = 0; j <= jmax; j++) m = fmaxf(m, p[j].x);
        float Z = 0.f;
        for (int j = 0; j <= jmax; j++) {
            float2 v = p[j];
            if (v.x > -1e30f) Z += v.y * __expf(v.x - m);
        }
        st = make_float2(m, 1.f / Z);
    }

    for (int ck = 0; ck < NK; ck++) {
        int cur = ck & 1;
        int k0 = ck * 32;
        CP_WAIT0();
        __syncthreads();

        {
            const float* rawS = (const float*)(avs + cur * 18432);
            bool needMask = (ck >= maskC);
            float4 p[4];
            #pragma unroll
            for (int g = 0; g < 4; g++) {
                float4 v = *(const float4*)&rawS[row * 36 + cs + g * 4];
                if (!needMask) {
                    p[g].x = __expf(v.x - st.x) * st.y;
                    p[g].y = __expf(v.y - st.x) * st.y;
                    p[g].z = __expf(v.z - st.x) * st.y;
                    p[g].w = __expf(v.w - st.x) * st.y;
                } else {
                    int c0 = k0 + cs + g * 4;
                    p[g].x = (c0 + 0 <= rowG) ? __expf(v.x - st.x) * st.y : 0.f;
                    p[g].y = (c0 + 1 <= rowG) ? __expf(v.y - st.x) * st.y : 0.f;
                    p[g].z = (c0 + 2 <= rowG) ? __expf(v.z - st.x) * st.y : 0.f;
                    p[g].w = (c0 + 3 <= rowG) ? __expf(v.w - st.x) * st.y : 0.f;
                }
                __stcs((float4*)&P[(size_t)rowG * Ll + k0 + cs + g * 4], p[g]);
            }
            uint2 h0, l0, h1, l1, h2, l2, h3, l3;
            split_f4(p[0], h0, l0);
            split_f4(p[1], h1, l1);
            split_f4(p[2], h2, l2);
            split_f4(p[3], h3, l3);
            *(uint4*)&AhS[row * 40 + cs] = make_uint4(h0.x, h0.y, h1.x, h1.y);
            *(uint4*)&AhS[row * 40 + cs + 8] = make_uint4(h2.x, h2.y, h3.x, h3.y);
            *(uint4*)&AlS[row * 40 + cs] = make_uint4(l0.x, l0.y, l1.x, l1.y);
            *(uint4*)&AlS[row * 40 + cs + 8] = make_uint4(l2.x, l2.y, l3.x, l3.y);
        }

        if (ck + 1 < NK) {
            av_prefetch(sb, cur ^ 1, (ck + 1) * 32, P, Vh, Vl, vB,
                        rowG, row, cs, krow, cseg);
            CP_COMMIT();
        }
        __syncthreads();

        uint32_t vhB = sb + 57344 + cur * 9216;
        #pragma unroll
        for (int kk = 0; kk < 2; kk++) {
            uint32_t afh[2][4], afl[2][4];
            #pragma unroll
            for (int i = 0; i < 2; i++) {
                ldsm_x4(sb + 36864 + aoff + kk * 32 + i * 1280,
                        afh[i][0], afh[i][1], afh[i][2], afh[i][3]);
                ldsm_x4(sb + 47104 + aoff + kk * 32 + i * 1280,
                        afl[i][0], afl[i][1], afl[i][2], afl[i][3]);
            }
            #pragma unroll
            for (int j = 0; j < 2; j++) {
                uint32_t bh0, bh1, bh2, bh3, bl0, bl1, bl2, bl3;
                ldsm_x4_t(vhB + boff + kk * 2304 + j * 32, bh0, bh1, bh2, bh3);
                ldsm_x4_t(vhB + 4608 + boff + kk * 2304 + j * 32, bl0, bl1, bl2, bl3);
                #pragma unroll
                for (int i = 0; i < 2; i++) {
                    mma_bf16(c[i][2 * j], afh[i], bh0, bh1);
                    mma_bf16(c[i][2 * j], afh[i], bl0, bl1);
                    mma_bf16(c[i][2 * j], afl[i], bh0, bh1);
                    mma_bf16(c[i][2 * j + 1], afh[i], bh2, bh3);
                    mma_bf16(c[i][2 * j + 1], afh[i], bl2, bl3);
                    mma_bf16(c[i][2 * j + 1], afl[i], bh2, bh3);
                }
            }
        }
    }

    int r = lane >> 2, cl2 = (lane & 3) * 2;
    #pragma unroll
    for (int i = 0; i < 2; i++) {
        int orow = rowBase + m0 + i * 16 + r;
        #pragma unroll
        for (int j = 0; j < 4; j++) {
            int col = n0 + j * 8 + cl2;
            size_t off0 = (size_t)(b * Ll + orow) * Dd + h * 64 + col;
            size_t off1 = (size_t)(b * Ll + orow + 8) * Dd + h * 64 + col;
            uint32_t hh, ll;
            pack_split2(c[i][j][0], c[i][j][1], hh, ll);
            *(uint32_t*)&Oh[off0] = hh;
            *(uint32_t*)&Ol[off0] = ll;
            pack_split2(c[i][j][2], c[i][j][3], hh, ll);
            *(uint32_t*)&Oh[off1] = hh;
            *(uint32_t*)&Ol[off1] = ll;
        }
    }
}

// ---------------- launch ----------------
extern "C" void kernel_launch(void* const* d_in, const int* in_sizes, int n_in,
                              void* d_out, int out_size)
{
    const float* x   = (const float*)d_in[0];
    const float* Wq  = (const float*)d_in[1];
    const float* bq  = (const float*)d_in[2];
    const float* Wk  = (const float*)d_in[3];
    const float* bk  = (const float*)d_in[4];
    const float* Wv  = (const float*)d_in[5];
    const float* bv  = (const float*)d_in[6];
    const float* Wo  = (const float*)d_in[7];
    const float* bo  = (const float*)d_in[8];
    const float* lsc = (const float*)d_in[9];
    const float* gsc = (const float*)d_in[10];

    float* out   = (float*)d_out;
    float* attnL = out + (size_t)MLEN * Dd;
    float* attnG = attnL + (size_t)Bb * LH * Ll * Ll;

    uint16_t *xh, *xl, *Wqh, *Wql, *Wkh, *Wkl, *Wvh, *Wvl, *Woh, *Wol;
    uint16_t *Qh, *Ql, *Kh, *Kl, *Vh, *Vl, *Ohp, *Olp;
    float2 *bst;
    cudaGetSymbolAddress((void**)&xh, g_xh);   cudaGetSymbolAddress((void**)&xl, g_xl);
    cudaGetSymbolAddress((void**)&Wqh, g_Wqh); cudaGetSymbolAddress((void**)&Wql, g_Wql);
    cudaGetSymbolAddress((void**)&Wkh, g_Wkh); cudaGetSymbolAddress((void**)&Wkl, g_Wkl);
    cudaGetSymbolAddress((void**)&Wvh, g_Wvh); cudaGetSymbolAddress((void**)&Wvl, g_Wvl);
    cudaGetSymbolAddress((void**)&Woh, g_Woh); cudaGetSymbolAddress((void**)&Wol, g_Wol);
    cudaGetSymbolAddress((void**)&Qh, g_Qh);   cudaGetSymbolAddress((void**)&Ql, g_Ql);
    cudaGetSymbolAddress((void**)&Kh, g_Kh);   cudaGetSymbolAddress((void**)&Kl, g_Kl);
    cudaGetSymbolAddress((void**)&Vh, g_Vh);   cudaGetSymbolAddress((void**)&Vl, g_Vl);
    cudaGetSymbolAddress((void**)&Ohp, g_Oh);  cudaGetSymbolAddress((void**)&Olp, g_Ol);
    cudaGetSymbolAddress((void**)&bst, g_bstats);

    cudaFuncSetAttribute(scores_mma, cudaFuncAttributeMaxDynamicSharedMemorySize, SC_SMEM);
    cudaFuncSetAttribute(av_mma, cudaFuncAttributeMaxDynamicSharedMemorySize, AV_SMEM);
    cudaFuncSetAttribute(gemm_qkv, cudaFuncAttributeMaxDynamicSharedMemorySize, GEMM_SMEM);
    cudaFuncSetAttribute(gemm_out, cudaFuncAttributeMaxDynamicSharedMemorySize, GEMM_SMEM);

    static cudaStream_t s2 = nullptr;
    static cudaEvent_t evFork = nullptr, evSplit = nullptr, evV = nullptr;
    if (!s2) {
        cudaStreamCreateWithFlags(&s2, cudaStreamNonBlocking);
        cudaEventCreateWithFlags(&evFork, cudaEventDisableTiming);
        cudaEventCreateWithFlags(&evSplit, cudaEventDisableTiming);
        cudaEventCreateWithFlags(&evV, cudaEventDisableTiming);
    }

    int nx4 = MLEN * Dd / 4;
    int nw4 = Dd * Dd / 4;

    // fork s2; zerofill has no data deps
    cudaEventRecord(evFork, 0);
    cudaStreamWaitEvent(s2, evFork, 0);
    zerofill_kernel<<<1920, 256, 0, s2>>>(attnL);

    split_kernel<<<nx4 / 256, 256>>>((const float4*)x, (uint2*)xh, (uint2*)xl, nx4);
    split4_kernel<<<dim3(nw4 / 256, 1, 4), 256>>>(
        (const float4*)Wq, (uint2*)Wqh, (uint2*)Wql,
        (const float4*)Wk, (uint2*)Wkh, (uint2*)Wkl,
        (const float4*)Wv, (uint2*)Wvh, (uint2*)Wvl,
        (const float4*)Wo, (uint2*)Woh, (uint2*)Wol, nw4);
    cudaEventRecord(evSplit, 0);
    cudaStreamWaitEvent(s2, evSplit, 0);

    // V-projection on s2 (only needed by av_mma)
    gemm_qkv<<<dim3(8, 32, 1), 256, GEMM_SMEM, s2>>>(xh, xl,
        Wvh, Wvl, bv, Vh, Vl,
        Wvh, Wvl, bv, Vh, Vl,
        Wvh, Wvl, bv, Vh, Vl);
    cudaEventRecord(evV, s2);

    // Q,K projections on main
    gemm_qkv<<<dim3(8, 32, 2), 256, GEMM_SMEM>>>(xh, xl,
        Wqh, Wql, bq, Qh, Ql,
        Wkh, Wkl, bk, Kh, Kl,
        Wkh, Wkl, bk, Kh, Kl);

    scores_mma<<<dim3(16, 16, 32), 256, SC_SMEM>>>(Qh, Ql, Kh, Kl, lsc, gsc,
                                                   attnL, attnG, bst);

    cudaStreamWaitEvent(0, evV, 0);   // join V (and zerofill) before AV
    av_mma<<<dim3(16, 32), 256, AV_SMEM>>>(attnL, attnG, Vh, Vl, bst, Ohp, Olp);

    gemm_out<<<dim3(8, 32), 256, GEMM_SMEM>>>(Ohp, Olp, Woh, Wol, bo, out);
}